// round 16
// baseline (speedup 1.0000x reference)
#include <cuda_runtime.h>
#include <cstdint>

#define TOKENS 65536
#define KCODES 1024
#define DDIM   64
#define HW     4096
#define TM     128
#define TN     128
#define NCH    (KCODES / TN)
#define NTILES (TOKENS / TM)                 // 512
#define GRID   296                           // 2 per SM, single resident wave

#define FRAG_U4 (8 * 16 * 32)                // per chunk: 4096 uint4 {bh0,bh1,bl0,bl1}
#define FRAG_B  (FRAG_U4 * 16)               // 65536 B

#define SM_IDX  0                            // 128 ints
#define SM_TILE 512                          // 1 int (tile broadcast)
#define SM_HNP  1024                         // 8 chunks x 64 float2 = 4096 B
#define SM_ALO  5120                         // 8 warps x 8 s x 32 lanes x 16 B = 32 KB
#define SM_BUF  (SM_ALO + 32768)             // 64 KB fragment buffer / A staging
#define SMEM_TOTAL (SM_BUF + FRAG_B)         // 103424 B -> 2 CTAs/SM

__device__ uint4  g_bfr[NCH * FRAG_U4];      // fragment-ordered codebook (hi|lo)
__device__ float2 g_hnp[NCH * 64];           // negated half-norm pairs per (j,tig)
__device__ int    g_tile;                    // persistent work queue head

__device__ __forceinline__ uint32_t f2tf32(float v) {
    uint32_t r; asm("cvt.rna.tf32.f32 %0, %1;" : "=r"(r) : "f"(v)); return r;
}

// One-shot prep: fragments + norm pairs + work-queue reset (runs before vq_tc
// on every graph replay, so the counter is re-armed each launch).
__global__ void vq_prep(const float* __restrict__ cb) {
    int idx = blockIdx.x * 256 + threadIdx.x;
    if (idx == 0) g_tile = 0;
    if (idx < 512) {                          // hnp: ch = idx>>6, pair = idx&63
        int ch = idx >> 6, pe = idx & 63;
        int j = pe >> 2, tig = pe & 3;
        int c = ch * TN + j * 8 + tig * 2;
        float s0 = 0.f, s1 = 0.f;
        #pragma unroll 8
        for (int k = 0; k < DDIM; ++k) {
            float a = cb[c * DDIM + k], b = cb[(c + 1) * DDIM + k];
            s0 += a * a; s1 += b * b;
        }
        g_hnp[ch * 64 + pe] = make_float2(-0.5f * s0, -0.5f * s1);
    } else if (idx < 512 + NCH * TN * DDIM) {
        int f = idx - 512;
        int ch = f >> 13, rem = f & 8191;
        int n = rem >> 6, k = rem & 63;
        float v = cb[(ch * TN + n) * DDIM + k];
        uint32_t hi = f2tf32(v);
        uint32_t lo = f2tf32(v - __uint_as_float(hi));
        int s = k >> 3, j = n >> 3;
        int ln = (n & 7) * 4 + (k & 3), half = (k >> 2) & 1;
        uint32_t* base = (uint32_t*)(g_bfr + (ch * 128 + s * 16 + j) * 32 + ln);
        base[half] = hi;
        base[2 + half] = lo;
    }
}

#define MMA(d, a0, a1, a2, a3, b0, b1)                                        \
    asm("mma.sync.aligned.m16n8k8.row.col.f32.tf32.tf32.f32 "                 \
        "{%0,%1,%2,%3}, {%4,%5,%6,%7}, {%8,%9}, {%0,%1,%2,%3};"               \
        : "+f"((d)[0]), "+f"((d)[1]), "+f"((d)[2]), "+f"((d)[3])              \
        : "r"(a0), "r"(a1), "r"(a2), "r"(a3), "r"(b0), "r"(b1))

#define CP16(dst, src) \
    asm volatile("cp.async.cg.shared.global [%0], [%1], 16;" \
                 :: "r"(dst), "l"(src) : "memory")

#define BETTER(v, c, bv, bi) \
    if ((v) > (bv) || ((v) == (bv) && (c) < (bi))) { (bv) = (v); (bi) = (c); }

// Persistent-CTA main: tile queue kills the wave tail; per chunk one cp.async
// staging group + 2 barriers; acc seeded with -0.5|c|^2.
__global__ __launch_bounds__(256, 2)
void vq_tc(const float* __restrict__ inp, const float* __restrict__ cb,
           float* __restrict__ out, int out_size) {
    extern __shared__ char smem[];
    int*    sidx  = (int*)(smem + SM_IDX);
    int*    stile = (int*)(smem + SM_TILE);
    float2* shnp  = (float2*)(smem + SM_HNP);
    float*  araw  = (float*)(smem + SM_BUF);    // [128][65] transient A staging
    uint32_t sbase = (uint32_t)__cvta_generic_to_shared(smem);

    int tid = threadIdx.x, wid = tid >> 5, lane = tid & 31;
    int gid = lane >> 2, tig = lane & 3;
    int r0w = wid * 16 + gid, r1w = r0w + 8;
    uint32_t alo_base = sbase + SM_ALO + wid * 4096 + lane * 16;

    // Stage all norm pairs once (4 KB)
    for (int e = tid; e < NCH * 64; e += 256) shnp[e] = g_hnp[e];

    for (;;) {
        if (tid == 0) *stile = atomicAdd(&g_tile, 1);
        __syncthreads();
        int tile = *stile;
        if (tile >= NTILES) break;

        int n0 = tile * TM;
        int b = n0 >> 12, s0 = n0 & (HW - 1);
        const float* ibase = inp + (long long)b * DDIM * HW + s0;

        for (int e = tid; e < TM * DDIM; e += 256) {
            int t = e & 127, d = e >> 7;
            araw[t * 65 + d] = ibase[d * HW + t];
        }
        __syncthreads();

        uint32_t ahi[8][4];
        #pragma unroll
        for (int s = 0; s < 8; ++s) {           // ahi -> regs, alo -> per-warp smem
            float v[4] = { araw[r0w * 65 + s * 8 + tig],     araw[r1w * 65 + s * 8 + tig],
                           araw[r0w * 65 + s * 8 + tig + 4], araw[r1w * 65 + s * 8 + tig + 4] };
            uint32_t lo[4];
            #pragma unroll
            for (int i = 0; i < 4; ++i) {
                ahi[s][i] = f2tf32(v[i]);
                lo[i] = f2tf32(v[i] - __uint_as_float(ahi[s][i]));
            }
            asm volatile("st.shared.v4.b32 [%0], {%1,%2,%3,%4};"
                         :: "r"(alo_base + s * 512 - lane * 16 + lane * 16),
                            "r"(lo[0]), "r"(lo[1]), "r"(lo[2]), "r"(lo[3]) : "memory");
        }
        __syncthreads();                         // araw dead; frag buffer reusable

        float best0 = -3.4e38f, best1 = -3.4e38f;
        int bi0 = 0, bi1 = 0;

        for (int ch = 0; ch < NCH; ++ch) {
            {   // stage this chunk's fragments: 16 x 16B per thread, one group
                uint32_t dst = sbase + SM_BUF;
                const char* src = (const char*)(g_bfr + ch * FRAG_U4);
                #pragma unroll
                for (int i = 0; i < 16; ++i)
                    CP16(dst + (tid + i * 256) * 16, src + (tid + i * 256) * 16);
                asm volatile("cp.async.commit_group;" ::: "memory");
                asm volatile("cp.async.wait_group 0;" ::: "memory");
            }
            __syncthreads();

            const uint4* frag = (const uint4*)(smem + SM_BUF) + lane;
            int c0 = ch * TN;

            float acc[16][4];
            #pragma unroll
            for (int j = 0; j < 16; ++j) {       // seed with -0.5|c|^2
                float2 h = shnp[ch * 64 + j * 4 + tig];
                acc[j][0] = h.x; acc[j][1] = h.y;
                acc[j][2] = h.x; acc[j][3] = h.y;
            }

            #pragma unroll
            for (int s = 0; s < 8; ++s) {
                uint32_t al[4];
                asm volatile("ld.shared.v4.b32 {%0,%1,%2,%3}, [%4];"
                             : "=r"(al[0]), "=r"(al[1]), "=r"(al[2]), "=r"(al[3])
                             : "r"(alo_base + s * 512));
                #pragma unroll
                for (int j = 0; j < 16; ++j) {
                    uint4 bf = frag[(s * 16 + j) * 32];
                    MMA(acc[j], ahi[s][0], ahi[s][1], ahi[s][2], ahi[s][3], bf.x, bf.y);
                    MMA(acc[j], ahi[s][0], ahi[s][1], ahi[s][2], ahi[s][3], bf.z, bf.w);
                    MMA(acc[j], al[0], al[1], al[2], al[3], bf.x, bf.y);
                }
            }

            // Running argmax, exact lowest-index tie-break
            #pragma unroll
            for (int j = 0; j < 16; ++j) {
                int colb = c0 + j * 8 + tig * 2;
                BETTER(acc[j][0], colb,     best0, bi0);
                BETTER(acc[j][1], colb + 1, best0, bi0);
                BETTER(acc[j][2], colb,     best1, bi1);
                BETTER(acc[j][3], colb + 1, best1, bi1);
            }
            __syncthreads();                     // all warps done before restage
        }

        // Quad reduce (lanes differing in tig hold different columns)
        #pragma unroll
        for (int m = 1; m <= 2; m <<= 1) {
            float ov; int oi;
            ov = __shfl_xor_sync(0xffffffffu, best0, m);
            oi = __shfl_xor_sync(0xffffffffu, bi0, m);
            if (ov > best0 || (ov == best0 && oi < bi0)) { best0 = ov; bi0 = oi; }
            ov = __shfl_xor_sync(0xffffffffu, best1, m);
            oi = __shfl_xor_sync(0xffffffffu, bi1, m);
            if (ov > best1 || (ov == best1 && oi < bi1)) { best1 = ov; bi1 = oi; }
        }
        if (tig == 0) { sidx[r0w] = bi0; sidx[r1w] = bi1; }
        __syncthreads();

        // Fused gather: out[b][d][s0+t] = cb[idx[t]][d]
        for (int e = tid; e < TM * DDIM; e += 256) {
            int d = e >> 7, t = e & 127;
            out[((long long)b * DDIM + d) * HW + s0 + t] = cb[sidx[t] * DDIM + d];
        }
        if (out_size > TOKENS * DDIM && tid < TM)
            out[TOKENS * DDIM + n0 + tid] = (float)sidx[tid];
        // next iteration's stile-sync orders sidx/araw reuse
    }
}

extern "C" void kernel_launch(void* const* d_in, const int* in_sizes, int n_in,
                              void* d_out, int out_size) {
    const float* inp = (const float*)d_in[0];   // (16, 64, 64, 64) f32
    const float* cb  = (const float*)d_in[1];   // (1024, 64) f32
    float* out = (float*)d_out;

    cudaFuncSetAttribute(vq_tc, cudaFuncAttributeMaxDynamicSharedMemorySize, SMEM_TOTAL);

    vq_prep<<<(512 + NCH * TN * DDIM + 255) / 256, 256>>>(cb);
    vq_tc<<<GRID, 256, SMEM_TOTAL>>>(inp, cb, out, out_size);
}

// round 17
// speedup vs baseline: 1.6245x; 1.6245x over previous
#include <cuda_runtime.h>
#include <cstdint>

#define TOKENS 65536
#define KCODES 1024
#define DDIM   64
#define HW     4096
#define TM     128
#define TN     64
#define NCH    (KCODES / TN)                 // 16

#define FRAG_U4C (8 * 8 * 32)                // per chunk: 2048 uint4 {bh0,bh1,bl0,bl1}
#define FRAG_BC  (FRAG_U4C * 16)             // 32768 B

#define SM_IDX  0                            // 128 ints
#define SM_HNP  512                          // 16 chunks x 32 float2 = 4096 B
#define SM_ARAW 4608                         // 128 x 65 floats = 33280 B
#define SM_BUF  38912                        // 2 x 32 KB fragment buffers (1KB aligned)
#define SMEM_TOTAL (SM_BUF + 2 * FRAG_BC)    // 104448 B -> 2 CTAs/SM

__device__ uint4  g_bfr[NCH * FRAG_U4C];     // fragment-ordered codebook (hi|lo)
__device__ float2 g_hnp[NCH * 32];           // negated half-norm pairs per (j,tig)

__device__ __forceinline__ uint32_t f2tf32(float v) {
    uint32_t r; asm("cvt.rna.tf32.f32 %0, %1;" : "=r"(r) : "f"(v)); return r;
}

// One-shot prep: interleaved tf32 hi/lo fragments + negated half-norm pairs.
__global__ void vq_prep(const float* __restrict__ cb) {
    int idx = blockIdx.x * 256 + threadIdx.x;
    if (idx < 512) {                          // hnp: ch = idx>>5, pair = idx&31
        int ch = idx >> 5, pe = idx & 31;
        int j = pe >> 2, tig = pe & 3;
        int c = ch * TN + j * 8 + tig * 2;
        float s0 = 0.f, s1 = 0.f;
        #pragma unroll 8
        for (int k = 0; k < DDIM; ++k) {
            float a = cb[c * DDIM + k], b = cb[(c + 1) * DDIM + k];
            s0 += a * a; s1 += b * b;
        }
        g_hnp[ch * 32 + pe] = make_float2(-0.5f * s0, -0.5f * s1);
    } else if (idx < 512 + KCODES * DDIM) {
        int f = idx - 512;
        int c = f >> 6, k = f & 63;           // code, k-dim
        int ch = c >> 6, n = c & 63;
        float v = cb[c * DDIM + k];
        uint32_t hi = f2tf32(v);
        uint32_t lo = f2tf32(v - __uint_as_float(hi));
        int s = k >> 3, j = n >> 3;
        int ln = (n & 7) * 4 + (k & 3), half = (k >> 2) & 1;
        uint32_t* base = (uint32_t*)(g_bfr + (ch * 64 + s * 8 + j) * 32 + ln);
        base[half] = hi;
        base[2 + half] = lo;
    }
}

#define MMA(d, a0, a1, a2, a3, b0, b1)                                        \
    asm("mma.sync.aligned.m16n8k8.row.col.f32.tf32.tf32.f32 "                 \
        "{%0,%1,%2,%3}, {%4,%5,%6,%7}, {%8,%9}, {%0,%1,%2,%3};"               \
        : "+f"((d)[0]), "+f"((d)[1]), "+f"((d)[2]), "+f"((d)[3])              \
        : "r"(a0), "r"(a1), "r"(a2), "r"(a3), "r"(b0), "r"(b1))

#define CP16(dst, src) \
    asm volatile("cp.async.cg.shared.global [%0], [%1], 16;" \
                 :: "r"(dst), "l"(src) : "memory")

#define BETTER(v, c, bv, bi) \
    if ((v) > (bv) || ((v) == (bv) && (c) < (bi))) { (bv) = (v); (bi) = (c); }

// Prefetch one 32KB chunk (8 x 16B per thread) into buffer buf and commit.
#define PREFETCH(ch_, buf_) do {                                              \
    uint32_t _d = sbase + SM_BUF + (buf_) * FRAG_BC;                          \
    const char* _s = (const char*)(g_bfr + (ch_) * FRAG_U4C);                 \
    _Pragma("unroll")                                                         \
    for (int _i = 0; _i < 8; ++_i)                                            \
        CP16(_d + (tid + _i * 256) * 16, _s + (tid + _i * 256) * 16);         \
    asm volatile("cp.async.commit_group;" ::: "memory");                      \
} while (0)

// Main: occ 2, TN=64 double-buffered pipeline — staging hidden behind mma;
// A hi+lo fragments fully register-resident; acc seeded with -0.5|c|^2.
__global__ __launch_bounds__(256, 2)
void vq_tc(const float* __restrict__ inp, const float* __restrict__ cb,
           float* __restrict__ out, int out_size) {
    extern __shared__ char smem[];
    int*    sidx = (int*)(smem + SM_IDX);
    float2* shnp = (float2*)(smem + SM_HNP);
    float*  araw = (float*)(smem + SM_ARAW);
    uint32_t sbase = (uint32_t)__cvta_generic_to_shared(smem);

    int tid = threadIdx.x, wid = tid >> 5, lane = tid & 31;
    int gid = lane >> 2, tig = lane & 3;
    int r0w = wid * 16 + gid, r1w = r0w + 8;
    int n0 = blockIdx.x * TM;
    int b = n0 >> 12, s0 = n0 & (HW - 1);
    const float* ibase = inp + (long long)b * DDIM * HW + s0;

    for (int e = tid; e < TM * DDIM; e += 256) {
        int t = e & 127, d = e >> 7;
        araw[t * 65 + d] = ibase[d * HW + t];
    }
    for (int e = tid; e < NCH * 32; e += 256) shnp[e] = g_hnp[e];
    __syncthreads();

    // Start the pipeline before A extraction (staging overlaps cvt work)
    PREFETCH(0, 0);
    PREFETCH(1, 1);

    uint32_t ahi[8][4], alo[8][4];
    #pragma unroll
    for (int s = 0; s < 8; ++s) {
        float v[4] = { araw[r0w * 65 + s * 8 + tig],     araw[r1w * 65 + s * 8 + tig],
                       araw[r0w * 65 + s * 8 + tig + 4], araw[r1w * 65 + s * 8 + tig + 4] };
        #pragma unroll
        for (int i = 0; i < 4; ++i) {
            ahi[s][i] = f2tf32(v[i]);
            alo[s][i] = f2tf32(v[i] - __uint_as_float(ahi[s][i]));
        }
    }

    float best0 = -3.4e38f, best1 = -3.4e38f;
    int bi0 = 0, bi1 = 0;

    #pragma unroll 1
    for (int ch = 0; ch < NCH; ++ch) {
        if (ch < NCH - 1)
            asm volatile("cp.async.wait_group 1;" ::: "memory");
        else
            asm volatile("cp.async.wait_group 0;" ::: "memory");
        __syncthreads();                       // buffer (ch&1) staged for all

        const uint4* frag = (const uint4*)(smem + SM_BUF + (ch & 1) * FRAG_BC) + lane;
        int c0 = ch * TN;

        float acc[8][4];
        #pragma unroll
        for (int j = 0; j < 8; ++j) {          // seed with -0.5|c|^2
            float2 h = shnp[ch * 32 + j * 4 + tig];
            acc[j][0] = h.x; acc[j][1] = h.y;
            acc[j][2] = h.x; acc[j][3] = h.y;
        }

        #pragma unroll
        for (int s = 0; s < 8; ++s)
            #pragma unroll
            for (int j = 0; j < 8; ++j) {
                uint4 bf = frag[(s * 8 + j) * 32];
                MMA(acc[j], ahi[s][0], ahi[s][1], ahi[s][2], ahi[s][3], bf.x, bf.y);
                MMA(acc[j], ahi[s][0], ahi[s][1], ahi[s][2], ahi[s][3], bf.z, bf.w);
                MMA(acc[j], alo[s][0], alo[s][1], alo[s][2], alo[s][3], bf.x, bf.y);
            }

        // Running argmax, exact lowest-index tie-break
        #pragma unroll
        for (int j = 0; j < 8; ++j) {
            int colb = c0 + j * 8 + tig * 2;
            BETTER(acc[j][0], colb,     best0, bi0);
            BETTER(acc[j][1], colb + 1, best0, bi0);
            BETTER(acc[j][2], colb,     best1, bi1);
            BETTER(acc[j][3], colb + 1, best1, bi1);
        }
        __syncthreads();                       // all warps done with buffer (ch&1)
        if (ch + 2 < NCH) PREFETCH(ch + 2, ch & 1);
    }

    // Quad reduce (lanes differing in tig hold different columns)
    #pragma unroll
    for (int m = 1; m <= 2; m <<= 1) {
        float ov; int oi;
        ov = __shfl_xor_sync(0xffffffffu, best0, m);
        oi = __shfl_xor_sync(0xffffffffu, bi0, m);
        if (ov > best0 || (ov == best0 && oi < bi0)) { best0 = ov; bi0 = oi; }
        ov = __shfl_xor_sync(0xffffffffu, best1, m);
        oi = __shfl_xor_sync(0xffffffffu, bi1, m);
        if (ov > best1 || (ov == best1 && oi < bi1)) { best1 = ov; bi1 = oi; }
    }
    if (tig == 0) { sidx[r0w] = bi0; sidx[r1w] = bi1; }
    __syncthreads();

    // Fused gather: out[b][d][s0+t] = cb[idx[t]][d]; coalesced writes, L2-hot reads.
    for (int e = tid; e < TM * DDIM; e += 256) {
        int d = e >> 7, t = e & 127;
        out[((long long)b * DDIM + d) * HW + s0 + t] = cb[sidx[t] * DDIM + d];
    }
    if (out_size > TOKENS * DDIM && tid < TM)
        out[TOKENS * DDIM + n0 + tid] = (float)sidx[tid];
}

extern "C" void kernel_launch(void* const* d_in, const int* in_sizes, int n_in,
                              void* d_out, int out_size) {
    const float* inp = (const float*)d_in[0];   // (16, 64, 64, 64) f32
    const float* cb  = (const float*)d_in[1];   // (1024, 64) f32
    float* out = (float*)d_out;

    cudaFuncSetAttribute(vq_tc, cudaFuncAttributeMaxDynamicSharedMemorySize, SMEM_TOTAL);

    vq_prep<<<(512 + KCODES * DDIM + 255) / 256, 256>>>(cb);
    vq_tc<<<TOKENS / TM, 256, SMEM_TOTAL>>>(inp, cb, out, out_size);
}